// round 5
// baseline (speedup 1.0000x reference)
#include <cuda_runtime.h>
#include <cstdint>

#define N_NODES 100000
#define OUTW 68
typedef unsigned long long u64;

__device__ float g_nsum[(size_t)N_NODES * 64];
__device__ float g_deg[N_NODES];
__device__ unsigned g_pmaskbits[3136];
__device__ int g_list[N_NODES];
__device__ int g_cnt;

// ---- packed-f32 helpers (FFMA2; sm_103a) -----------------------------------
__device__ __forceinline__ u64 pack2(float a, float b) {
    u64 r; asm("mov.b64 %0, {%1, %2};" : "=l"(r) : "f"(a), "f"(b)); return r;
}
__device__ __forceinline__ void ffma2(u64& d, u64 a, u64 b) {
    asm("fma.rn.f32x2 %0, %1, %2, %3;" : "=l"(d) : "l"(a), "l"(b), "l"(d));
}
__device__ __forceinline__ void unpack2(u64 v, float& a, float& b) {
    asm("mov.b64 {%0, %1}, %2;" : "=f"(a), "=f"(b) : "l"(v));
}

// ---------------------------------------------------------------------------
// Kernel 1: softmax gate -> bit mask, zero deg, zero nsum rows of masked nodes
// ---------------------------------------------------------------------------
__global__ void pmask_kernel(const float* __restrict__ ops) {
    int n = blockIdx.x * blockDim.x + threadIdx.x;
    if (n == 0) g_cnt = 0;
    bool msk = false;
    if (n < N_NODES) {
        float o0 = ops[n * 4 + 0], o1 = ops[n * 4 + 1];
        float o2 = ops[n * 4 + 2], o3 = ops[n * 4 + 3];
        float mx = fmaxf(fmaxf(o0, o1), fmaxf(o2, o3));
        float e0 = expf(o0 - mx), e1 = expf(o1 - mx);
        float e2 = expf(o2 - mx), e3 = expf(o3 - mx);
        float p0 = e0 / (e0 + e1 + e2 + e3);
        msk = (p0 > 0.5f);
        g_deg[n] = 0.f;
    }
    unsigned bits = __ballot_sync(0xffffffffu, msk);
    if ((threadIdx.x & 31) == 0 && (n & ~31) < N_NODES)
        g_pmaskbits[n >> 5] = bits;
    if (msk) {
        float4 z = make_float4(0.f, 0.f, 0.f, 0.f);
        float4* row = reinterpret_cast<float4*>(g_nsum) + (size_t)n * 16;
        #pragma unroll
        for (int c = 0; c < 16; c++) row[c] = z;
    }
}

// ---------------------------------------------------------------------------
// Kernel 2: gated edge scatter, ballot redistribution 4 items/iter
// (8 lanes per item, 2 float4 chunks per lane).
// ---------------------------------------------------------------------------
__global__ void edge_kernel(const int* __restrict__ ei,
                            const float4* __restrict__ feat4,
                            int E) {
    int t = blockIdx.x * blockDim.x + threadIdx.x;
    int lane = threadIdx.x & 31;
    bool active = false;
    int tgt = 0, srcn = 0;
    if (t < 2 * E) {
        int e = t >> 1, dir = t & 1;
        int s = __ldg(&ei[e]);
        int d = __ldg(&ei[E + e]);
        tgt  = dir ? d : s;
        srcn = dir ? s : d;
        active = (g_pmaskbits[tgt >> 5] >> (tgt & 31)) & 1;
    }
    unsigned m = __ballot_sync(0xffffffffu, active);
    float4* nsum4 = reinterpret_cast<float4*>(g_nsum);
    int grp = lane >> 3;
    int c = lane & 7;
    while (m) {
        int b0 = -1, b1 = -1, b2 = -1, b3 = -1;
        b0 = __ffs(m) - 1; m &= m - 1;
        if (m) { b1 = __ffs(m) - 1; m &= m - 1; }
        if (m) { b2 = __ffs(m) - 1; m &= m - 1; }
        if (m) { b3 = __ffs(m) - 1; m &= m - 1; }
        int myb = (grp == 0) ? b0 : (grp == 1) ? b1 : (grp == 2) ? b2 : b3;
        int bb = (myb >= 0) ? myb : b0;
        int T = __shfl_sync(0xffffffffu, tgt,  bb);
        int S = __shfl_sync(0xffffffffu, srcn, bb);
        if (myb >= 0) {
            float4 v0 = __ldg(&feat4[(size_t)S * 16 + c]);
            float4 v1 = __ldg(&feat4[(size_t)S * 16 + c + 8]);
            asm volatile("red.global.add.v4.f32 [%0], {%1,%2,%3,%4};" ::
                         "l"(nsum4 + (size_t)T * 16 + c),
                         "f"(v0.x), "f"(v0.y), "f"(v0.z), "f"(v0.w) : "memory");
            asm volatile("red.global.add.v4.f32 [%0], {%1,%2,%3,%4};" ::
                         "l"(nsum4 + (size_t)T * 16 + c + 8),
                         "f"(v1.x), "f"(v1.y), "f"(v1.z), "f"(v1.w) : "memory");
            if (c == 0) atomicAdd(&g_deg[T], 1.f);
        }
    }
}

// ---------------------------------------------------------------------------
// Kernel 3: compact active nodes (warp-aggregated atomic)
// ---------------------------------------------------------------------------
__global__ void compact_kernel() {
    int n = blockIdx.x * blockDim.x + threadIdx.x;
    int lane = threadIdx.x & 31;
    bool act = false;
    if (n < N_NODES)
        act = ((g_pmaskbits[n >> 5] >> (n & 31)) & 1) && (g_deg[n] > 0.f);
    unsigned m = __ballot_sync(0xffffffffu, act);
    int base = 0;
    if (lane == 0 && m) base = atomicAdd(&g_cnt, __popc(m));
    base = __shfl_sync(0xffffffffu, base, 0);
    if (act) g_list[base + __popc(m & ((1u << lane) - 1))] = n;
}

// ---------------------------------------------------------------------------
// Kernel 4: MLP. Activations stored in smem as DUPLICATED pairs (v,v) so the
// FFMA2 inner loops need zero packing MOVs: LDS.128 weights + LDS.128 act
// (two dup pairs = 2 k-steps) + FFMA2 only.
// ---------------------------------------------------------------------------
#define WARPS 24
#define THREADS (WARPS * 32)
#define NPW 4

#define OFF_W1   0          // 128*128
#define OFF_B1   16384      // 128
#define OFF_W2   16512      // 128*64
#define OFF_B2   24704      // 64
#define OFF_W3   24768      // 64*67
#define OFF_B3   29056      // 67 (+1 pad)
#define OFF_P1   29124      // 64*32
#define OFF_PB1  31172      // 32
#define OFF_P2   31204      // 32
#define OFF_PB2  31236      // 1 (+3 pad)
#define OFF_SCR  31240      // per-warp: NPW*128 u64 = 1024 floats
#define SMEM_FLOATS (OFF_SCR + WARPS * NPW * 256)

__global__ void __launch_bounds__(THREADS, 1)
mlp_kernel(const float* __restrict__ nf,
           const float* __restrict__ W1, const float* __restrict__ b1,
           const float* __restrict__ W2, const float* __restrict__ b2,
           const float* __restrict__ W3, const float* __restrict__ b3,
           const float* __restrict__ P1, const float* __restrict__ pb1,
           const float* __restrict__ P2, const float* __restrict__ pb2,
           float* __restrict__ out) {
    extern __shared__ float sm[];
    int tid = threadIdx.x;

    for (int i = tid; i < 16384; i += THREADS) sm[OFF_W1 + i] = W1[i];
    for (int i = tid; i < 128;   i += THREADS) sm[OFF_B1 + i] = b1[i];
    for (int i = tid; i < 8192;  i += THREADS) sm[OFF_W2 + i] = W2[i];
    for (int i = tid; i < 64;    i += THREADS) sm[OFF_B2 + i] = b2[i];
    for (int i = tid; i < 4288;  i += THREADS) sm[OFF_W3 + i] = W3[i];
    for (int i = tid; i < 67;    i += THREADS) sm[OFF_B3 + i] = b3[i];
    for (int i = tid; i < 2048;  i += THREADS) sm[OFF_P1 + i] = P1[i];
    for (int i = tid; i < 32;    i += THREADS) sm[OFF_PB1 + i] = pb1[i];
    for (int i = tid; i < 32;    i += THREADS) sm[OFF_P2 + i] = P2[i];
    if (tid == 0) sm[OFF_PB2] = pb2[0];
    __syncthreads();

    int warpId = tid >> 5;
    int lane   = tid & 31;
    // per-warp activation buffer: NPW * 128 dup-pairs (u64)
    u64*    bufu = reinterpret_cast<u64*>(sm + OFF_SCR) + warpId * (NPW * 128);
    float*  buff = reinterpret_cast<float*>(bufu);          // scalar view
    float2* buf2 = reinterpret_cast<float2*>(bufu);
    float4* buf4 = reinterpret_cast<float4*>(bufu);

    const ulonglong2* sW1u = reinterpret_cast<const ulonglong2*>(sm + OFF_W1);
    const float4*     sb1_4 = reinterpret_cast<const float4*>(sm + OFF_B1);
    const u64*        sW2u = reinterpret_cast<const u64*>(sm + OFF_W2);
    const float2*     sb2_2 = reinterpret_cast<const float2*>(sm + OFF_B2);

    const int cnt = g_cnt;
    const int totalWarps = gridDim.x * WARPS;

    for (int g = blockIdx.x * WARPS + warpId; g * NPW < cnt; g += totalWarps) {
        int nn[NPW];
        bool valid[NPW];
        #pragma unroll
        for (int q = 0; q < NPW; q++) {
            int li = g * NPW + q;
            valid[q] = li < cnt;
            nn[q] = g_list[valid[q] ? li : g * NPW];
        }

        // ---- ctx = [feat | nmean], stored duplicated ----
        #pragma unroll
        for (int q = 0; q < NPW; q++) {
            int n = nn[q];
            float inv = 1.f / fmaxf(g_deg[n], 1.f);
            float v0 = nf[(size_t)n * 64 + lane];
            float v1 = nf[(size_t)n * 64 + 32 + lane];
            float v2 = g_nsum[(size_t)n * 64 + lane] * inv;
            float v3 = g_nsum[(size_t)n * 64 + 32 + lane] * inv;
            buf2[q * 128 + lane]      = make_float2(v0, v0);
            buf2[q * 128 + 32 + lane] = make_float2(v1, v1);
            buf2[q * 128 + 64 + lane] = make_float2(v2, v2);
            buf2[q * 128 + 96 + lane] = make_float2(v3, v3);
        }
        __syncwarp();

        // ---- layer 1: 128 -> 128 relu, FFMA2, 2 k per iter ----
        u64 acc01[NPW], acc23[NPW];
        {
            float4 bb = sb1_4[lane];
            u64 i01 = pack2(bb.x, bb.y), i23 = pack2(bb.z, bb.w);
            #pragma unroll
            for (int q = 0; q < NPW; q++) { acc01[q] = i01; acc23[q] = i23; }
        }
        #pragma unroll 4
        for (int i2 = 0; i2 < 64; i2++) {
            ulonglong2 w0 = sW1u[(2 * i2)     * 32 + lane];
            ulonglong2 w1 = sW1u[(2 * i2 + 1) * 32 + lane];
            #pragma unroll
            for (int q = 0; q < NPW; q++) {
                ulonglong2 cc = reinterpret_cast<const ulonglong2*>(
                                    bufu + q * 128)[i2];
                ffma2(acc01[q], w0.x, cc.x);
                ffma2(acc23[q], w0.y, cc.x);
                ffma2(acc01[q], w1.x, cc.y);
                ffma2(acc23[q], w1.y, cc.y);
            }
        }
        __syncwarp();
        #pragma unroll
        for (int q = 0; q < NPW; q++) {
            float a0, a1, a2v, a3;
            unpack2(acc01[q], a0, a1);
            unpack2(acc23[q], a2v, a3);
            a0 = fmaxf(a0, 0.f); a1 = fmaxf(a1, 0.f);
            a2v = fmaxf(a2v, 0.f); a3 = fmaxf(a3, 0.f);
            buf4[q * 64 + 2 * lane + 0] = make_float4(a0, a0, a1, a1);
            buf4[q * 64 + 2 * lane + 1] = make_float4(a2v, a2v, a3, a3);
        }
        __syncwarp();

        // ---- layer 2: 128 -> 64 relu, FFMA2, 2 k per iter ----
        u64 acc2[NPW];
        {
            float2 bb = sb2_2[lane];
            u64 ii = pack2(bb.x, bb.y);
            #pragma unroll
            for (int q = 0; q < NPW; q++) acc2[q] = ii;
        }
        #pragma unroll 4
        for (int i2 = 0; i2 < 64; i2++) {
            u64 wk0 = sW2u[(2 * i2)     * 32 + lane];
            u64 wk1 = sW2u[(2 * i2 + 1) * 32 + lane];
            #pragma unroll
            for (int q = 0; q < NPW; q++) {
                ulonglong2 cc = reinterpret_cast<const ulonglong2*>(
                                    bufu + q * 128)[i2];
                ffma2(acc2[q], wk0, cc.x);
                ffma2(acc2[q], wk1, cc.y);
            }
        }
        __syncwarp();
        #pragma unroll
        for (int q = 0; q < NPW; q++) {
            float b0v, b1v;
            unpack2(acc2[q], b0v, b1v);
            b0v = fmaxf(b0v, 0.f); b1v = fmaxf(b1v, 0.f);
            buf4[q * 64 + lane] = make_float4(b0v, b0v, b1v, b1v);
        }
        __syncwarp();

        // ---- layer 3: 64 -> 67 (reads dup pairs, 2 k per LDS.128) ----
        float ga[NPW], gb2[NPW], gc[NPW];
        {
            float bA = sm[OFF_B3 + lane];
            float bB = sm[OFF_B3 + 32 + lane];
            float bC = (lane < 3) ? sm[OFF_B3 + 64 + lane] : 0.f;
            #pragma unroll
            for (int q = 0; q < NPW; q++) { ga[q] = bA; gb2[q] = bB; gc[q] = bC; }
        }
        #pragma unroll 4
        for (int i2 = 0; i2 < 32; i2++) {
            int k0 = 2 * i2, k1 = 2 * i2 + 1;
            float w1a = sm[OFF_W3 + k0 * 67 + lane];
            float w2a = sm[OFF_W3 + k0 * 67 + 32 + lane];
            float w3a = (lane < 3) ? sm[OFF_W3 + k0 * 67 + 64 + lane] : 0.f;
            float w1b = sm[OFF_W3 + k1 * 67 + lane];
            float w2b = sm[OFF_W3 + k1 * 67 + 32 + lane];
            float w3b = (lane < 3) ? sm[OFF_W3 + k1 * 67 + 64 + lane] : 0.f;
            #pragma unroll
            for (int q = 0; q < NPW; q++) {
                float4 c4 = buf4[q * 64 + i2];
                ga[q]  += c4.x * w1a + c4.z * w1b;
                gb2[q] += c4.x * w2a + c4.z * w2b;
                gc[q]  += c4.x * w3a + c4.z * w3b;
            }
        }
        __syncwarp();
        // write layer-3 output as scalars (float view)
        #pragma unroll
        for (int q = 0; q < NPW; q++) {
            buff[q * 256 + lane]      = ga[q];
            buff[q * 256 + 32 + lane] = gb2[q];
            if (lane < 3) buff[q * 256 + 64 + lane] = gc[q];
        }
        __syncwarp();

        // ---- head: feats = buff[3..66] -> 32 relu -> 1 sigmoid ----
        float pa[NPW];
        {
            float bb = sm[OFF_PB1 + lane];
            #pragma unroll
            for (int q = 0; q < NPW; q++) pa[q] = bb;
        }
        #pragma unroll 4
        for (int i = 0; i < 64; i++) {
            float w = sm[OFF_P1 + i * 32 + lane];
            #pragma unroll
            for (int q = 0; q < NPW; q++) pa[q] += buff[q * 256 + 3 + i] * w;
        }
        float prob[NPW];
        float w2s = sm[OFF_P2 + lane];
        float pb2v = sm[OFF_PB2];
        #pragma unroll
        for (int q = 0; q < NPW; q++) {
            float v = fmaxf(pa[q], 0.f) * w2s;
            #pragma unroll
            for (int o = 16; o > 0; o >>= 1)
                v += __shfl_xor_sync(0xffffffffu, v, o);
            prob[q] = 1.f / (1.f + expf(-(v + pb2v)));
        }

        // ---- write out ----
        #pragma unroll
        for (int q = 0; q < NPW; q++) {
            if (!valid[q]) continue;
            float* o = out + (size_t)nn[q] * OUTW;
            o[lane]      = buff[q * 256 + lane];
            o[32 + lane] = buff[q * 256 + 32 + lane];
            if (lane < 3) o[64 + lane] = buff[q * 256 + 64 + lane];
            if (lane == 3) o[67] = prob[q];
        }
        __syncwarp();
    }
}

// ---------------------------------------------------------------------------
extern "C" void kernel_launch(void* const* d_in, const int* in_sizes, int n_in,
                              void* d_out, int out_size) {
    const float* nf  = (const float*)d_in[0];
    const float* ops = (const float*)d_in[1];
    const int*   ei  = (const int*)d_in[2];
    const float* W1  = (const float*)d_in[3];
    const float* b1  = (const float*)d_in[4];
    const float* W2  = (const float*)d_in[5];
    const float* b2  = (const float*)d_in[6];
    const float* W3  = (const float*)d_in[7];
    const float* b3  = (const float*)d_in[8];
    const float* P1  = (const float*)d_in[9];
    const float* pb1 = (const float*)d_in[10];
    const float* P2  = (const float*)d_in[11];
    const float* pb2 = (const float*)d_in[12];
    float* out = (float*)d_out;

    int E = in_sizes[2] / 2;

    cudaMemsetAsync(d_out, 0, (size_t)out_size * sizeof(float));

    pmask_kernel<<<(N_NODES + 255) / 256, 256>>>(ops);

    int tthreads = 2 * E;
    edge_kernel<<<(tthreads + 255) / 256, 256>>>(ei, (const float4*)nf, E);

    compact_kernel<<<(N_NODES + 255) / 256, 256>>>();

    static_assert(SMEM_FLOATS * 4 <= 227 * 1024, "smem");
    cudaFuncSetAttribute(mlp_kernel,
                         cudaFuncAttributeMaxDynamicSharedMemorySize,
                         SMEM_FLOATS * 4);
    mlp_kernel<<<152, THREADS, SMEM_FLOATS * 4>>>(
        nf, W1, b1, W2, b2, W3, b3, P1, pb1, P2, pb2, out);
}

// round 6
// speedup vs baseline: 1.0232x; 1.0232x over previous
#include <cuda_runtime.h>
#include <cstdint>

#define N_NODES 100000
#define OUTW 68
typedef unsigned long long u64;

__device__ float g_nsum[(size_t)N_NODES * 64];
__device__ float g_deg[N_NODES];
__device__ unsigned g_pmaskbits[3136];
__device__ int g_list[N_NODES];
__device__ int g_cnt;

// ---- packed-f32 helpers (FFMA2; sm_103a) -----------------------------------
__device__ __forceinline__ u64 pack2s(float v) {
    u64 r; asm("mov.b64 %0, {%1, %1};" : "=l"(r) : "f"(v)); return r;
}
__device__ __forceinline__ u64 pack2(float a, float b) {
    u64 r; asm("mov.b64 %0, {%1, %2};" : "=l"(r) : "f"(a), "f"(b)); return r;
}
__device__ __forceinline__ void ffma2(u64& d, u64 a, u64 b) {
    asm("fma.rn.f32x2 %0, %1, %2, %3;" : "=l"(d) : "l"(a), "l"(b), "l"(d));
}
__device__ __forceinline__ void unpack2(u64 v, float& a, float& b) {
    asm("mov.b64 {%0, %1}, %2;" : "=f"(a), "=f"(b) : "l"(v));
}

// ---------------------------------------------------------------------------
// Kernel 1: softmax gate -> bit mask, zero deg, zero nsum rows of masked nodes
// ---------------------------------------------------------------------------
__global__ void pmask_kernel(const float* __restrict__ ops) {
    int n = blockIdx.x * blockDim.x + threadIdx.x;
    if (n == 0) g_cnt = 0;
    bool msk = false;
    if (n < N_NODES) {
        float o0 = ops[n * 4 + 0], o1 = ops[n * 4 + 1];
        float o2 = ops[n * 4 + 2], o3 = ops[n * 4 + 3];
        float mx = fmaxf(fmaxf(o0, o1), fmaxf(o2, o3));
        float e0 = expf(o0 - mx), e1 = expf(o1 - mx);
        float e2 = expf(o2 - mx), e3 = expf(o3 - mx);
        float p0 = e0 / (e0 + e1 + e2 + e3);
        msk = (p0 > 0.5f);
        g_deg[n] = 0.f;
    }
    unsigned bits = __ballot_sync(0xffffffffu, msk);
    if ((threadIdx.x & 31) == 0 && (n & ~31) < N_NODES)
        g_pmaskbits[n >> 5] = bits;
    if (msk) {
        float4 z = make_float4(0.f, 0.f, 0.f, 0.f);
        float4* row = reinterpret_cast<float4*>(g_nsum) + (size_t)n * 16;
        #pragma unroll
        for (int c = 0; c < 16; c++) row[c] = z;
    }
}

// ---------------------------------------------------------------------------
// Kernel 2: gated edge scatter, ballot redistribution 4 items/iter
// (8 lanes per item, 2 float4 chunks per lane).
// ---------------------------------------------------------------------------
__global__ void edge_kernel(const int* __restrict__ ei,
                            const float4* __restrict__ feat4,
                            int E) {
    int t = blockIdx.x * blockDim.x + threadIdx.x;
    int lane = threadIdx.x & 31;
    bool active = false;
    int tgt = 0, srcn = 0;
    if (t < 2 * E) {
        int e = t >> 1, dir = t & 1;
        int s = __ldg(&ei[e]);
        int d = __ldg(&ei[E + e]);
        tgt  = dir ? d : s;
        srcn = dir ? s : d;
        active = (g_pmaskbits[tgt >> 5] >> (tgt & 31)) & 1;
    }
    unsigned m = __ballot_sync(0xffffffffu, active);
    float4* nsum4 = reinterpret_cast<float4*>(g_nsum);
    int grp = lane >> 3;
    int c = lane & 7;
    while (m) {
        int b0 = -1, b1 = -1, b2 = -1, b3 = -1;
        b0 = __ffs(m) - 1; m &= m - 1;
        if (m) { b1 = __ffs(m) - 1; m &= m - 1; }
        if (m) { b2 = __ffs(m) - 1; m &= m - 1; }
        if (m) { b3 = __ffs(m) - 1; m &= m - 1; }
        int myb = (grp == 0) ? b0 : (grp == 1) ? b1 : (grp == 2) ? b2 : b3;
        int bb = (myb >= 0) ? myb : b0;
        int T = __shfl_sync(0xffffffffu, tgt,  bb);
        int S = __shfl_sync(0xffffffffu, srcn, bb);
        if (myb >= 0) {
            float4 v0 = __ldg(&feat4[(size_t)S * 16 + c]);
            float4 v1 = __ldg(&feat4[(size_t)S * 16 + c + 8]);
            asm volatile("red.global.add.v4.f32 [%0], {%1,%2,%3,%4};" ::
                         "l"(nsum4 + (size_t)T * 16 + c),
                         "f"(v0.x), "f"(v0.y), "f"(v0.z), "f"(v0.w) : "memory");
            asm volatile("red.global.add.v4.f32 [%0], {%1,%2,%3,%4};" ::
                         "l"(nsum4 + (size_t)T * 16 + c + 8),
                         "f"(v1.x), "f"(v1.y), "f"(v1.z), "f"(v1.w) : "memory");
            if (c == 0) atomicAdd(&g_deg[T], 1.f);
        }
    }
}

// ---------------------------------------------------------------------------
// Kernel 3: compact active nodes (warp-aggregated atomic)
// ---------------------------------------------------------------------------
__global__ void compact_kernel() {
    int n = blockIdx.x * blockDim.x + threadIdx.x;
    int lane = threadIdx.x & 31;
    bool act = false;
    if (n < N_NODES)
        act = ((g_pmaskbits[n >> 5] >> (n & 31)) & 1) && (g_deg[n] > 0.f);
    unsigned m = __ballot_sync(0xffffffffu, act);
    int base = 0;
    if (lane == 0 && m) base = atomicAdd(&g_cnt, __popc(m));
    base = __shfl_sync(0xffffffffu, base, 0);
    if (act) g_list[base + __popc(m & ((1u << lane) - 1))] = n;
}

// ---------------------------------------------------------------------------
// Kernel 4: MLP, R4 math core (FFMA2 + register pack), 32 warps/block so
// every warp handles at most ONE 4-node group; float4 weight staging.
// ---------------------------------------------------------------------------
#define WARPS 32
#define THREADS (WARPS * 32)
#define NPW 4

#define OFF_W1   0          // 128*128
#define OFF_B1   16384      // 128
#define OFF_W2   16512      // 128*64
#define OFF_B2   24704      // 64
#define OFF_W3   24768      // 64*67
#define OFF_B3   29056      // 67 (+1 pad)
#define OFF_P1   29124      // 64*32
#define OFF_PB1  31172      // 32
#define OFF_P2   31204      // 32
#define OFF_PB2  31236      // 1 (+3 pad)
#define OFF_SCR  31240      // per-warp: NPW*128 floats (2 KB)
#define SMEM_FLOATS (OFF_SCR + WARPS * NPW * 128)

__global__ void __launch_bounds__(THREADS, 1)
mlp_kernel(const float* __restrict__ nf,
           const float* __restrict__ W1, const float* __restrict__ b1,
           const float* __restrict__ W2, const float* __restrict__ b2,
           const float* __restrict__ W3, const float* __restrict__ b3,
           const float* __restrict__ P1, const float* __restrict__ pb1,
           const float* __restrict__ P2, const float* __restrict__ pb2,
           float* __restrict__ out) {
    extern __shared__ float sm[];
    int tid = threadIdx.x;

    // ---- float4-vectorized staging of the big tables ----
    {
        float4* d1 = reinterpret_cast<float4*>(sm + OFF_W1);
        const float4* s1 = reinterpret_cast<const float4*>(W1);
        for (int i = tid; i < 4096; i += THREADS) d1[i] = s1[i];
        float4* d2 = reinterpret_cast<float4*>(sm + OFF_W2);
        const float4* s2 = reinterpret_cast<const float4*>(W2);
        for (int i = tid; i < 2048; i += THREADS) d2[i] = s2[i];
        float4* d3 = reinterpret_cast<float4*>(sm + OFF_W3);
        const float4* s3 = reinterpret_cast<const float4*>(W3);
        for (int i = tid; i < 1072; i += THREADS) d3[i] = s3[i];
        float4* d4 = reinterpret_cast<float4*>(sm + OFF_P1);
        const float4* s4 = reinterpret_cast<const float4*>(P1);
        for (int i = tid; i < 512; i += THREADS) d4[i] = s4[i];
    }
    for (int i = tid; i < 128; i += THREADS) sm[OFF_B1 + i] = b1[i];
    for (int i = tid; i < 64;  i += THREADS) sm[OFF_B2 + i] = b2[i];
    for (int i = tid; i < 67;  i += THREADS) sm[OFF_B3 + i] = b3[i];
    for (int i = tid; i < 32;  i += THREADS) sm[OFF_PB1 + i] = pb1[i];
    for (int i = tid; i < 32;  i += THREADS) sm[OFF_P2 + i] = P2[i];
    if (tid == 0) sm[OFF_PB2] = pb2[0];
    __syncthreads();

    int warpId = tid >> 5;
    int lane   = tid & 31;
    float* buf = sm + OFF_SCR + warpId * (NPW * 128);   // ping-pong [NPW][128]
    float4* buf4 = reinterpret_cast<float4*>(buf);

    const ulonglong2* sW1u = reinterpret_cast<const ulonglong2*>(sm + OFF_W1);
    const float4*     sb1_4 = reinterpret_cast<const float4*>(sm + OFF_B1);
    const u64*        sW2u = reinterpret_cast<const u64*>(sm + OFF_W2);
    const float2*     sb2_2 = reinterpret_cast<const float2*>(sm + OFF_B2);

    const int cnt = g_cnt;
    const int totalWarps = gridDim.x * WARPS;

    for (int g = blockIdx.x * WARPS + warpId; g * NPW < cnt; g += totalWarps) {
        int nn[NPW];
        bool valid[NPW];
        #pragma unroll
        for (int q = 0; q < NPW; q++) {
            int li = g * NPW + q;
            valid[q] = li < cnt;
            nn[q] = g_list[valid[q] ? li : g * NPW];
        }

        // ---- ctx = [feat | nmean] ----
        #pragma unroll
        for (int q = 0; q < NPW; q++) {
            int n = nn[q];
            float inv = 1.f / fmaxf(g_deg[n], 1.f);
            buf[q * 128 + lane]      = nf[(size_t)n * 64 + lane];
            buf[q * 128 + 32 + lane] = nf[(size_t)n * 64 + 32 + lane];
            buf[q * 128 + 64 + lane] = g_nsum[(size_t)n * 64 + lane] * inv;
            buf[q * 128 + 96 + lane] = g_nsum[(size_t)n * 64 + 32 + lane] * inv;
        }
        __syncwarp();

        // ---- layer 1: 128 -> 128 relu, FFMA2. lane owns outs 4*lane..+3 ----
        u64 acc01[NPW], acc23[NPW];
        {
            float4 bb = sb1_4[lane];
            u64 i01 = pack2(bb.x, bb.y), i23 = pack2(bb.z, bb.w);
            #pragma unroll
            for (int q = 0; q < NPW; q++) { acc01[q] = i01; acc23[q] = i23; }
        }
        #pragma unroll 4
        for (int i4 = 0; i4 < 32; i4++) {
            float4 c[NPW];
            #pragma unroll
            for (int q = 0; q < NPW; q++) c[q] = buf4[q * 32 + i4];
            #pragma unroll
            for (int k = 0; k < 4; k++) {
                ulonglong2 w = sW1u[(i4 * 4 + k) * 32 + lane];
                #pragma unroll
                for (int q = 0; q < NPW; q++) {
                    float cv = (k == 0) ? c[q].x : (k == 1) ? c[q].y
                             : (k == 2) ? c[q].z : c[q].w;
                    u64 cv2 = pack2s(cv);
                    ffma2(acc01[q], w.x, cv2);
                    ffma2(acc23[q], w.y, cv2);
                }
            }
        }
        __syncwarp();
        #pragma unroll
        for (int q = 0; q < NPW; q++) {
            float a0, a1, a2v, a3;
            unpack2(acc01[q], a0, a1);
            unpack2(acc23[q], a2v, a3);
            buf4[q * 32 + lane] = make_float4(fmaxf(a0, 0.f), fmaxf(a1, 0.f),
                                              fmaxf(a2v, 0.f), fmaxf(a3, 0.f));
        }
        __syncwarp();

        // ---- layer 2: 128 -> 64 relu, FFMA2. lane owns outs 2*lane..+1 ----
        u64 acc2[NPW];
        {
            float2 bb = sb2_2[lane];
            u64 ii = pack2(bb.x, bb.y);
            #pragma unroll
            for (int q = 0; q < NPW; q++) acc2[q] = ii;
        }
        #pragma unroll 4
        for (int i4 = 0; i4 < 32; i4++) {
            float4 c[NPW];
            #pragma unroll
            for (int q = 0; q < NPW; q++) c[q] = buf4[q * 32 + i4];
            #pragma unroll
            for (int k = 0; k < 4; k++) {
                u64 w = sW2u[(i4 * 4 + k) * 32 + lane];
                #pragma unroll
                for (int q = 0; q < NPW; q++) {
                    float cv = (k == 0) ? c[q].x : (k == 1) ? c[q].y
                             : (k == 2) ? c[q].z : c[q].w;
                    ffma2(acc2[q], w, pack2s(cv));
                }
            }
        }
        __syncwarp();
        #pragma unroll
        for (int q = 0; q < NPW; q++) {
            float a0, a1;
            unpack2(acc2[q], a0, a1);
            buf[q * 128 + 2 * lane + 0] = fmaxf(a0, 0.f);
            buf[q * 128 + 2 * lane + 1] = fmaxf(a1, 0.f);
        }
        __syncwarp();

        // ---- layer 3: 64 -> 67 ----
        float ga[NPW], gb2[NPW], gc[NPW];
        {
            float bA = sm[OFF_B3 + lane];
            float bB = sm[OFF_B3 + 32 + lane];
            float bC = (lane < 3) ? sm[OFF_B3 + 64 + lane] : 0.f;
            #pragma unroll
            for (int q = 0; q < NPW; q++) { ga[q] = bA; gb2[q] = bB; gc[q] = bC; }
        }
        #pragma unroll 2
        for (int i4 = 0; i4 < 16; i4++) {
            float4 c[NPW];
            #pragma unroll
            for (int q = 0; q < NPW; q++) c[q] = buf4[q * 32 + i4];
            #pragma unroll
            for (int k = 0; k < 4; k++) {
                int i = i4 * 4 + k;
                float w1 = sm[OFF_W3 + i * 67 + lane];
                float w2 = sm[OFF_W3 + i * 67 + 32 + lane];
                float w3 = (lane < 3) ? sm[OFF_W3 + i * 67 + 64 + lane] : 0.f;
                #pragma unroll
                for (int q = 0; q < NPW; q++) {
                    float cv = (k == 0) ? c[q].x : (k == 1) ? c[q].y
                             : (k == 2) ? c[q].z : c[q].w;
                    ga[q] += cv * w1; gb2[q] += cv * w2; gc[q] += cv * w3;
                }
            }
        }
        __syncwarp();
        #pragma unroll
        for (int q = 0; q < NPW; q++) {
            buf[q * 128 + lane]      = ga[q];
            buf[q * 128 + 32 + lane] = gb2[q];
            if (lane < 3) buf[q * 128 + 64 + lane] = gc[q];
        }
        __syncwarp();

        // ---- head: feats = buf[3..66] -> 32 relu -> 1 sigmoid ----
        float pa[NPW];
        {
            float bb = sm[OFF_PB1 + lane];
            #pragma unroll
            for (int q = 0; q < NPW; q++) pa[q] = bb;
        }
        #pragma unroll 2
        for (int i = 0; i < 64; i++) {
            float w = sm[OFF_P1 + i * 32 + lane];
            #pragma unroll
            for (int q = 0; q < NPW; q++) pa[q] += buf[q * 128 + 3 + i] * w;
        }
        float prob[NPW];
        float w2s = sm[OFF_P2 + lane];
        float pb2v = sm[OFF_PB2];
        #pragma unroll
        for (int q = 0; q < NPW; q++) {
            float v = fmaxf(pa[q], 0.f) * w2s;
            #pragma unroll
            for (int o = 16; o > 0; o >>= 1)
                v += __shfl_xor_sync(0xffffffffu, v, o);
            prob[q] = 1.f / (1.f + expf(-(v + pb2v)));
        }

        // ---- write out ----
        #pragma unroll
        for (int q = 0; q < NPW; q++) {
            if (!valid[q]) continue;
            float* o = out + (size_t)nn[q] * OUTW;
            o[lane]      = buf[q * 128 + lane];
            o[32 + lane] = buf[q * 128 + 32 + lane];
            if (lane < 3) o[64 + lane] = buf[q * 128 + 64 + lane];
            if (lane == 3) o[67] = prob[q];
        }
        __syncwarp();
    }
}

// ---------------------------------------------------------------------------
extern "C" void kernel_launch(void* const* d_in, const int* in_sizes, int n_in,
                              void* d_out, int out_size) {
    const float* nf  = (const float*)d_in[0];
    const float* ops = (const float*)d_in[1];
    const int*   ei  = (const int*)d_in[2];
    const float* W1  = (const float*)d_in[3];
    const float* b1  = (const float*)d_in[4];
    const float* W2  = (const float*)d_in[5];
    const float* b2  = (const float*)d_in[6];
    const float* W3  = (const float*)d_in[7];
    const float* b3  = (const float*)d_in[8];
    const float* P1  = (const float*)d_in[9];
    const float* pb1 = (const float*)d_in[10];
    const float* P2  = (const float*)d_in[11];
    const float* pb2 = (const float*)d_in[12];
    float* out = (float*)d_out;

    int E = in_sizes[2] / 2;

    cudaMemsetAsync(d_out, 0, (size_t)out_size * sizeof(float));

    pmask_kernel<<<(N_NODES + 255) / 256, 256>>>(ops);

    int tthreads = 2 * E;
    edge_kernel<<<(tthreads + 255) / 256, 256>>>(ei, (const float4*)nf, E);

    compact_kernel<<<(N_NODES + 255) / 256, 256>>>();

    static_assert(SMEM_FLOATS * 4 <= 227 * 1024, "smem");
    cudaFuncSetAttribute(mlp_kernel,
                         cudaFuncAttributeMaxDynamicSharedMemorySize,
                         SMEM_FLOATS * 4);
    mlp_kernel<<<152, THREADS, SMEM_FLOATS * 4>>>(
        nf, W1, b1, W2, b2, W3, b3, P1, pb1, P2, pb2, out);
}

// round 7
// speedup vs baseline: 1.0790x; 1.0546x over previous
#include <cuda_runtime.h>
#include <cstdint>

#define N_NODES 100000
#define OUTW 68
typedef unsigned long long u64;

__device__ float g_nsum[(size_t)N_NODES * 64];
__device__ float g_deg[N_NODES];
__device__ unsigned g_pmaskbits[3136];
__device__ int g_list[N_NODES];
__device__ int g_cnt;

// ---- packed-f32 helpers (FFMA2; sm_103a) -----------------------------------
__device__ __forceinline__ u64 pack2s(float v) {
    u64 r; asm("mov.b64 %0, {%1, %1};" : "=l"(r) : "f"(v)); return r;
}
__device__ __forceinline__ u64 pack2(float a, float b) {
    u64 r; asm("mov.b64 %0, {%1, %2};" : "=l"(r) : "f"(a), "f"(b)); return r;
}
__device__ __forceinline__ void ffma2(u64& d, u64 a, u64 b) {
    asm("fma.rn.f32x2 %0, %1, %2, %3;" : "=l"(d) : "l"(a), "l"(b), "l"(d));
}
__device__ __forceinline__ void unpack2(u64 v, float& a, float& b) {
    asm("mov.b64 {%0, %1}, %2;" : "=f"(a), "=f"(b) : "l"(v));
}

// ---------------------------------------------------------------------------
// Kernel 1: softmax gate -> bit mask, zero deg, zero nsum rows of masked nodes
// ---------------------------------------------------------------------------
__global__ void pmask_kernel(const float* __restrict__ ops) {
    int n = blockIdx.x * blockDim.x + threadIdx.x;
    if (n == 0) g_cnt = 0;
    bool msk = false;
    if (n < N_NODES) {
        float o0 = ops[n * 4 + 0], o1 = ops[n * 4 + 1];
        float o2 = ops[n * 4 + 2], o3 = ops[n * 4 + 3];
        float mx = fmaxf(fmaxf(o0, o1), fmaxf(o2, o3));
        float e0 = expf(o0 - mx), e1 = expf(o1 - mx);
        float e2 = expf(o2 - mx), e3 = expf(o3 - mx);
        float p0 = e0 / (e0 + e1 + e2 + e3);
        msk = (p0 > 0.5f);
        g_deg[n] = 0.f;
    }
    unsigned bits = __ballot_sync(0xffffffffu, msk);
    if ((threadIdx.x & 31) == 0 && (n & ~31) < N_NODES)
        g_pmaskbits[n >> 5] = bits;
    if (msk) {
        float4 z = make_float4(0.f, 0.f, 0.f, 0.f);
        float4* row = reinterpret_cast<float4*>(g_nsum) + (size_t)n * 16;
        #pragma unroll
        for (int c = 0; c < 16; c++) row[c] = z;
    }
}

// ---------------------------------------------------------------------------
// Kernel 2: gated edge scatter, ballot redistribution 4 items/iter
// ---------------------------------------------------------------------------
__global__ void edge_kernel(const int* __restrict__ ei,
                            const float4* __restrict__ feat4,
                            int E) {
    int t = blockIdx.x * blockDim.x + threadIdx.x;
    int lane = threadIdx.x & 31;
    bool active = false;
    int tgt = 0, srcn = 0;
    if (t < 2 * E) {
        int e = t >> 1, dir = t & 1;
        int s = __ldg(&ei[e]);
        int d = __ldg(&ei[E + e]);
        tgt  = dir ? d : s;
        srcn = dir ? s : d;
        active = (g_pmaskbits[tgt >> 5] >> (tgt & 31)) & 1;
    }
    unsigned m = __ballot_sync(0xffffffffu, active);
    float4* nsum4 = reinterpret_cast<float4*>(g_nsum);
    int grp = lane >> 3;
    int c = lane & 7;
    while (m) {
        int b0 = -1, b1 = -1, b2 = -1, b3 = -1;
        b0 = __ffs(m) - 1; m &= m - 1;
        if (m) { b1 = __ffs(m) - 1; m &= m - 1; }
        if (m) { b2 = __ffs(m) - 1; m &= m - 1; }
        if (m) { b3 = __ffs(m) - 1; m &= m - 1; }
        int myb = (grp == 0) ? b0 : (grp == 1) ? b1 : (grp == 2) ? b2 : b3;
        int bb = (myb >= 0) ? myb : b0;
        int T = __shfl_sync(0xffffffffu, tgt,  bb);
        int S = __shfl_sync(0xffffffffu, srcn, bb);
        if (myb >= 0) {
            float4 v0 = __ldg(&feat4[(size_t)S * 16 + c]);
            float4 v1 = __ldg(&feat4[(size_t)S * 16 + c + 8]);
            asm volatile("red.global.add.v4.f32 [%0], {%1,%2,%3,%4};" ::
                         "l"(nsum4 + (size_t)T * 16 + c),
                         "f"(v0.x), "f"(v0.y), "f"(v0.z), "f"(v0.w) : "memory");
            asm volatile("red.global.add.v4.f32 [%0], {%1,%2,%3,%4};" ::
                         "l"(nsum4 + (size_t)T * 16 + c + 8),
                         "f"(v1.x), "f"(v1.y), "f"(v1.z), "f"(v1.w) : "memory");
            if (c == 0) atomicAdd(&g_deg[T], 1.f);
        }
    }
}

// ---------------------------------------------------------------------------
// Kernel 3: compact active nodes (warp-aggregated atomic)
// ---------------------------------------------------------------------------
__global__ void compact_kernel() {
    int n = blockIdx.x * blockDim.x + threadIdx.x;
    int lane = threadIdx.x & 31;
    bool act = false;
    if (n < N_NODES)
        act = ((g_pmaskbits[n >> 5] >> (n & 31)) & 1) && (g_deg[n] > 0.f);
    unsigned m = __ballot_sync(0xffffffffu, act);
    int base = 0;
    if (lane == 0 && m) base = atomicAdd(&g_cnt, __popc(m));
    base = __shfl_sync(0xffffffffu, base, 0);
    if (act) g_list[base + __popc(m & ((1u << lane) - 1))] = n;
}

// ---------------------------------------------------------------------------
// Kernel 4: MLP. NPW=8 nodes/warp halves per-node weight-LDS traffic
// (the measured bottleneck). 16 warps/block -> 128-reg budget.
// ---------------------------------------------------------------------------
#define WARPS 16
#define THREADS (WARPS * 32)
#define NPW 8

#define OFF_W1   0          // 128*128
#define OFF_B1   16384      // 128
#define OFF_W2   16512      // 128*64
#define OFF_B2   24704      // 64
#define OFF_W3   24768      // 64*67
#define OFF_B3   29056      // 67 (+1 pad)
#define OFF_P1   29124      // 64*32
#define OFF_PB1  31172      // 32
#define OFF_P2   31204      // 32
#define OFF_PB2  31236      // 1 (+3 pad)
#define OFF_SCR  31240      // per-warp: NPW*128 floats (4 KB)
#define SMEM_FLOATS (OFF_SCR + WARPS * NPW * 128)

__global__ void __launch_bounds__(THREADS, 1)
mlp_kernel(const float* __restrict__ nf,
           const float* __restrict__ W1, const float* __restrict__ b1,
           const float* __restrict__ W2, const float* __restrict__ b2,
           const float* __restrict__ W3, const float* __restrict__ b3,
           const float* __restrict__ P1, const float* __restrict__ pb1,
           const float* __restrict__ P2, const float* __restrict__ pb2,
           float* __restrict__ out) {
    extern __shared__ float sm[];
    int tid = threadIdx.x;

    {
        float4* d1 = reinterpret_cast<float4*>(sm + OFF_W1);
        const float4* s1 = reinterpret_cast<const float4*>(W1);
        for (int i = tid; i < 4096; i += THREADS) d1[i] = s1[i];
        float4* d2 = reinterpret_cast<float4*>(sm + OFF_W2);
        const float4* s2 = reinterpret_cast<const float4*>(W2);
        for (int i = tid; i < 2048; i += THREADS) d2[i] = s2[i];
        float4* d3 = reinterpret_cast<float4*>(sm + OFF_W3);
        const float4* s3 = reinterpret_cast<const float4*>(W3);
        for (int i = tid; i < 1072; i += THREADS) d3[i] = s3[i];
        float4* d4 = reinterpret_cast<float4*>(sm + OFF_P1);
        const float4* s4 = reinterpret_cast<const float4*>(P1);
        for (int i = tid; i < 512; i += THREADS) d4[i] = s4[i];
    }
    for (int i = tid; i < 128; i += THREADS) sm[OFF_B1 + i] = b1[i];
    for (int i = tid; i < 64;  i += THREADS) sm[OFF_B2 + i] = b2[i];
    for (int i = tid; i < 67;  i += THREADS) sm[OFF_B3 + i] = b3[i];
    for (int i = tid; i < 32;  i += THREADS) sm[OFF_PB1 + i] = pb1[i];
    for (int i = tid; i < 32;  i += THREADS) sm[OFF_P2 + i] = P2[i];
    if (tid == 0) sm[OFF_PB2] = pb2[0];
    __syncthreads();

    int warpId = tid >> 5;
    int lane   = tid & 31;
    float* buf = sm + OFF_SCR + warpId * (NPW * 128);   // [NPW][128] ping-pong
    float4* buf4 = reinterpret_cast<float4*>(buf);      // [NPW][32]

    const ulonglong2* sW1u = reinterpret_cast<const ulonglong2*>(sm + OFF_W1);
    const float4*     sb1_4 = reinterpret_cast<const float4*>(sm + OFF_B1);
    const u64*        sW2u = reinterpret_cast<const u64*>(sm + OFF_W2);
    const float2*     sb2_2 = reinterpret_cast<const float2*>(sm + OFF_B2);

    const int cnt = g_cnt;
    const int totalWarps = gridDim.x * WARPS;

    for (int g = blockIdx.x * WARPS + warpId; g * NPW < cnt; g += totalWarps) {
        int nn[NPW];
        bool valid[NPW];
        #pragma unroll
        for (int q = 0; q < NPW; q++) {
            int li = g * NPW + q;
            valid[q] = li < cnt;
            nn[q] = g_list[valid[q] ? li : g * NPW];
        }

        // ---- ctx = [feat | nmean] ----
        #pragma unroll
        for (int q = 0; q < NPW; q++) {
            int n = nn[q];
            float inv = 1.f / fmaxf(g_deg[n], 1.f);
            buf[q * 128 + lane]      = nf[(size_t)n * 64 + lane];
            buf[q * 128 + 32 + lane] = nf[(size_t)n * 64 + 32 + lane];
            buf[q * 128 + 64 + lane] = g_nsum[(size_t)n * 64 + lane] * inv;
            buf[q * 128 + 96 + lane] = g_nsum[(size_t)n * 64 + 32 + lane] * inv;
        }
        __syncwarp();

        // ---- layer 1: 128 -> 128 relu, FFMA2. lane owns outs 4*lane..+3 ----
        u64 acc01[NPW], acc23[NPW];
        {
            float4 bb = sb1_4[lane];
            u64 i01 = pack2(bb.x, bb.y), i23 = pack2(bb.z, bb.w);
            #pragma unroll
            for (int q = 0; q < NPW; q++) { acc01[q] = i01; acc23[q] = i23; }
        }
        #pragma unroll 2
        for (int i4 = 0; i4 < 32; i4++) {
            #pragma unroll
            for (int k = 0; k < 4; k++) {
                ulonglong2 w = sW1u[(i4 * 4 + k) * 32 + lane];
                #pragma unroll
                for (int q = 0; q < NPW; q++) {
                    float4 c4 = buf4[q * 32 + i4];
                    float cv = (k == 0) ? c4.x : (k == 1) ? c4.y
                             : (k == 2) ? c4.z : c4.w;
                    u64 cv2 = pack2s(cv);
                    ffma2(acc01[q], w.x, cv2);
                    ffma2(acc23[q], w.y, cv2);
                }
            }
        }
        __syncwarp();
        #pragma unroll
        for (int q = 0; q < NPW; q++) {
            float a0, a1, a2v, a3;
            unpack2(acc01[q], a0, a1);
            unpack2(acc23[q], a2v, a3);
            buf4[q * 32 + lane] = make_float4(fmaxf(a0, 0.f), fmaxf(a1, 0.f),
                                              fmaxf(a2v, 0.f), fmaxf(a3, 0.f));
        }
        __syncwarp();

        // ---- layer 2: 128 -> 64 relu, FFMA2. lane owns outs 2*lane..+1 ----
        u64 acc2[NPW];
        {
            float2 bb = sb2_2[lane];
            u64 ii = pack2(bb.x, bb.y);
            #pragma unroll
            for (int q = 0; q < NPW; q++) acc2[q] = ii;
        }
        #pragma unroll 2
        for (int i4 = 0; i4 < 32; i4++) {
            #pragma unroll
            for (int k = 0; k < 4; k++) {
                u64 w = sW2u[(i4 * 4 + k) * 32 + lane];
                #pragma unroll
                for (int q = 0; q < NPW; q++) {
                    float4 c4 = buf4[q * 32 + i4];
                    float cv = (k == 0) ? c4.x : (k == 1) ? c4.y
                             : (k == 2) ? c4.z : c4.w;
                    ffma2(acc2[q], w, pack2s(cv));
                }
            }
        }
        __syncwarp();
        #pragma unroll
        for (int q = 0; q < NPW; q++) {
            float a0, a1;
            unpack2(acc2[q], a0, a1);
            buf[q * 128 + 2 * lane + 0] = fmaxf(a0, 0.f);
            buf[q * 128 + 2 * lane + 1] = fmaxf(a1, 0.f);
        }
        __syncwarp();

        // ---- layer 3: 64 -> 67. lane owns outs lane, lane+32, lane+64(<3) ----
        float ga[NPW], gb2[NPW], gc[NPW];
        {
            float bA = sm[OFF_B3 + lane];
            float bB = sm[OFF_B3 + 32 + lane];
            float bC = (lane < 3) ? sm[OFF_B3 + 64 + lane] : 0.f;
            #pragma unroll
            for (int q = 0; q < NPW; q++) { ga[q] = bA; gb2[q] = bB; gc[q] = bC; }
        }
        #pragma unroll 2
        for (int i4 = 0; i4 < 16; i4++) {
            #pragma unroll
            for (int k = 0; k < 4; k++) {
                int i = i4 * 4 + k;
                float w1 = sm[OFF_W3 + i * 67 + lane];
                float w2 = sm[OFF_W3 + i * 67 + 32 + lane];
                float w3 = (lane < 3) ? sm[OFF_W3 + i * 67 + 64 + lane] : 0.f;
                #pragma unroll
                for (int q = 0; q < NPW; q++) {
                    float4 c4 = buf4[q * 32 + i4];
                    float cv = (k == 0) ? c4.x : (k == 1) ? c4.y
                             : (k == 2) ? c4.z : c4.w;
                    ga[q] += cv * w1; gb2[q] += cv * w2; gc[q] += cv * w3;
                }
            }
        }
        __syncwarp();

        // ---- write pos/feats to gmem NOW (frees regs), feats ALIGNED to buf:
        //      feat[j] = out[3+j] stored at buf[q*128 + j] ----
        #pragma unroll
        for (int q = 0; q < NPW; q++) {
            if (valid[q]) {
                float* o = out + (size_t)nn[q] * OUTW;
                o[lane]      = ga[q];
                o[32 + lane] = gb2[q];
                if (lane < 3) o[64 + lane] = gc[q];
            }
            if (lane >= 3) buf[q * 128 + lane - 3] = ga[q];
            buf[q * 128 + lane + 29] = gb2[q];
            if (lane < 3) buf[q * 128 + lane + 61] = gc[q];
        }
        __syncwarp();

        // ---- head: feats(64, aligned) -> 32 relu -> 1 sigmoid ----
        float pa[NPW];
        {
            float bb = sm[OFF_PB1 + lane];
            #pragma unroll
            for (int q = 0; q < NPW; q++) pa[q] = bb;
        }
        #pragma unroll 2
        for (int i4 = 0; i4 < 16; i4++) {
            #pragma unroll
            for (int k = 0; k < 4; k++) {
                float w = sm[OFF_P1 + (i4 * 4 + k) * 32 + lane];
                #pragma unroll
                for (int q = 0; q < NPW; q++) {
                    float4 c4 = buf4[q * 32 + i4];
                    float cv = (k == 0) ? c4.x : (k == 1) ? c4.y
                             : (k == 2) ? c4.z : c4.w;
                    pa[q] += cv * w;
                }
            }
        }
        float w2s = sm[OFF_P2 + lane];
        float pb2v = sm[OFF_PB2];
        #pragma unroll
        for (int q = 0; q < NPW; q++) {
            float v = fmaxf(pa[q], 0.f) * w2s;
            #pragma unroll
            for (int o = 16; o > 0; o >>= 1)
                v += __shfl_xor_sync(0xffffffffu, v, o);
            if (lane == 0 && valid[q])
                out[(size_t)nn[q] * OUTW + 67] =
                    1.f / (1.f + expf(-(v + pb2v)));
        }
        __syncwarp();
    }
}

// ---------------------------------------------------------------------------
extern "C" void kernel_launch(void* const* d_in, const int* in_sizes, int n_in,
                              void* d_out, int out_size) {
    const float* nf  = (const float*)d_in[0];
    const float* ops = (const float*)d_in[1];
    const int*   ei  = (const int*)d_in[2];
    const float* W1  = (const float*)d_in[3];
    const float* b1  = (const float*)d_in[4];
    const float* W2  = (const float*)d_in[5];
    const float* b2  = (const float*)d_in[6];
    const float* W3  = (const float*)d_in[7];
    const float* b3  = (const float*)d_in[8];
    const float* P1  = (const float*)d_in[9];
    const float* pb1 = (const float*)d_in[10];
    const float* P2  = (const float*)d_in[11];
    const float* pb2 = (const float*)d_in[12];
    float* out = (float*)d_out;

    int E = in_sizes[2] / 2;

    cudaMemsetAsync(d_out, 0, (size_t)out_size * sizeof(float));

    pmask_kernel<<<(N_NODES + 255) / 256, 256>>>(ops);

    int tthreads = 2 * E;
    edge_kernel<<<(tthreads + 255) / 256, 256>>>(ei, (const float4*)nf, E);

    compact_kernel<<<(N_NODES + 255) / 256, 256>>>();

    static_assert(SMEM_FLOATS * 4 <= 227 * 1024, "smem");
    cudaFuncSetAttribute(mlp_kernel,
                         cudaFuncAttributeMaxDynamicSharedMemorySize,
                         SMEM_FLOATS * 4);
    mlp_kernel<<<152, THREADS, SMEM_FLOATS * 4>>>(
        nf, W1, b1, W2, b2, W3, b3, P1, pb1, P2, pb2, out);
}

// round 8
// speedup vs baseline: 1.0832x; 1.0039x over previous
#include <cuda_runtime.h>
#include <cstdint>

#define N_NODES 100000
#define OUTW 68
typedef unsigned long long u64;

__device__ float g_nsum[(size_t)N_NODES * 64];
__device__ float g_deg[N_NODES];
__device__ unsigned g_pmaskbits[3136];
__device__ int g_list[N_NODES];
__device__ int g_cnt;

// ---- packed-f32 helpers (FFMA2; sm_103a) -----------------------------------
__device__ __forceinline__ u64 pack2(float a, float b) {
    u64 r; asm("mov.b64 %0, {%1, %2};" : "=l"(r) : "f"(a), "f"(b)); return r;
}
__device__ __forceinline__ void ffma2(u64& d, u64 a, u64 b) {
    asm("fma.rn.f32x2 %0, %1, %2, %3;" : "=l"(d) : "l"(a), "l"(b), "l"(d));
}
__device__ __forceinline__ float psum(u64 v) {   // lo + hi
    float a, b;
    asm("mov.b64 {%0, %1}, %2;" : "=f"(a), "=f"(b) : "l"(v));
    return a + b;
}

// ---------------------------------------------------------------------------
// Kernel 1: softmax gate -> bit mask, zero deg, zero nsum rows of masked nodes
// ---------------------------------------------------------------------------
__global__ void pmask_kernel(const float* __restrict__ ops) {
    int n = blockIdx.x * blockDim.x + threadIdx.x;
    if (n == 0) g_cnt = 0;
    bool msk = false;
    if (n < N_NODES) {
        float o0 = ops[n * 4 + 0], o1 = ops[n * 4 + 1];
        float o2 = ops[n * 4 + 2], o3 = ops[n * 4 + 3];
        float mx = fmaxf(fmaxf(o0, o1), fmaxf(o2, o3));
        float e0 = expf(o0 - mx), e1 = expf(o1 - mx);
        float e2 = expf(o2 - mx), e3 = expf(o3 - mx);
        float p0 = e0 / (e0 + e1 + e2 + e3);
        msk = (p0 > 0.5f);
        g_deg[n] = 0.f;
    }
    unsigned bits = __ballot_sync(0xffffffffu, msk);
    if ((threadIdx.x & 31) == 0 && (n & ~31) < N_NODES)
        g_pmaskbits[n >> 5] = bits;
    if (msk) {
        float4 z = make_float4(0.f, 0.f, 0.f, 0.f);
        float4* row = reinterpret_cast<float4*>(g_nsum) + (size_t)n * 16;
        #pragma unroll
        for (int c = 0; c < 16; c++) row[c] = z;
    }
}

// ---------------------------------------------------------------------------
// Kernel 2: gated edge scatter, ballot redistribution 4 items/iter
// ---------------------------------------------------------------------------
__global__ void edge_kernel(const int* __restrict__ ei,
                            const float4* __restrict__ feat4,
                            int E) {
    int t = blockIdx.x * blockDim.x + threadIdx.x;
    int lane = threadIdx.x & 31;
    bool active = false;
    int tgt = 0, srcn = 0;
    if (t < 2 * E) {
        int e = t >> 1, dir = t & 1;
        int s = __ldg(&ei[e]);
        int d = __ldg(&ei[E + e]);
        tgt  = dir ? d : s;
        srcn = dir ? s : d;
        active = (g_pmaskbits[tgt >> 5] >> (tgt & 31)) & 1;
    }
    unsigned m = __ballot_sync(0xffffffffu, active);
    float4* nsum4 = reinterpret_cast<float4*>(g_nsum);
    int grp = lane >> 3;
    int c = lane & 7;
    while (m) {
        int b0 = -1, b1 = -1, b2 = -1, b3 = -1;
        b0 = __ffs(m) - 1; m &= m - 1;
        if (m) { b1 = __ffs(m) - 1; m &= m - 1; }
        if (m) { b2 = __ffs(m) - 1; m &= m - 1; }
        if (m) { b3 = __ffs(m) - 1; m &= m - 1; }
        int myb = (grp == 0) ? b0 : (grp == 1) ? b1 : (grp == 2) ? b2 : b3;
        int bb = (myb >= 0) ? myb : b0;
        int T = __shfl_sync(0xffffffffu, tgt,  bb);
        int S = __shfl_sync(0xffffffffu, srcn, bb);
        if (myb >= 0) {
            float4 v0 = __ldg(&feat4[(size_t)S * 16 + c]);
            float4 v1 = __ldg(&feat4[(size_t)S * 16 + c + 8]);
            asm volatile("red.global.add.v4.f32 [%0], {%1,%2,%3,%4};" ::
                         "l"(nsum4 + (size_t)T * 16 + c),
                         "f"(v0.x), "f"(v0.y), "f"(v0.z), "f"(v0.w) : "memory");
            asm volatile("red.global.add.v4.f32 [%0], {%1,%2,%3,%4};" ::
                         "l"(nsum4 + (size_t)T * 16 + c + 8),
                         "f"(v1.x), "f"(v1.y), "f"(v1.z), "f"(v1.w) : "memory");
            if (c == 0) atomicAdd(&g_deg[T], 1.f);
        }
    }
}

// ---------------------------------------------------------------------------
// Kernel 3: compact active nodes (warp-aggregated atomic)
// ---------------------------------------------------------------------------
__global__ void compact_kernel() {
    int n = blockIdx.x * blockDim.x + threadIdx.x;
    int lane = threadIdx.x & 31;
    bool act = false;
    if (n < N_NODES)
        act = ((g_pmaskbits[n >> 5] >> (n & 31)) & 1) && (g_deg[n] > 0.f);
    unsigned m = __ballot_sync(0xffffffffu, act);
    int base = 0;
    if (lane == 0 && m) base = atomicAdd(&g_cnt, __popc(m));
    base = __shfl_sync(0xffffffffu, base, 0);
    if (act) g_list[base + __popc(m & ((1u << lane) - 1))] = n;
}

// ---------------------------------------------------------------------------
// Kernel 4: MLP with K-paired FFMA2: acc(lo,hi) += (W[2t],W[2t+1])*(c[2t],c[2t+1]),
// out = lo+hi. Weights staged into paired [t][j] u64 layout; activations read
// as natural contiguous LDS.128 pairs -> ZERO packing MOVs in all layers.
// NPW=6 matches active-count/warp-count so each warp runs <= 1 group.
// ---------------------------------------------------------------------------
#define WARPS 16
#define THREADS (WARPS * 32)
#define NPW 6

#define OFF_W1   0          // u64[64][128] = 16384 floats
#define OFF_W2   16384      // u64[64][64]  = 8192
#define OFF_W3   24576      // u64[32][68]  = 4352
#define OFF_P1   28928      // u64[32][32]  = 2048
#define OFF_B1   30976      // 128
#define OFF_B2   31104      // 64
#define OFF_B3   31168      // 68 (67 + pad)
#define OFF_PB1  31236      // 32
#define OFF_P2   31268      // 32
#define OFF_PB2  31300      // 1 (+3 pad)
#define OFF_SCR  31304      // per-warp: NPW*128 floats (3 KB)
#define SMEM_FLOATS (OFF_SCR + WARPS * NPW * 128)

__global__ void __launch_bounds__(THREADS, 1)
mlp_kernel(const float* __restrict__ nf,
           const float* __restrict__ W1, const float* __restrict__ b1,
           const float* __restrict__ W2, const float* __restrict__ b2,
           const float* __restrict__ W3, const float* __restrict__ b3,
           const float* __restrict__ P1, const float* __restrict__ pb1,
           const float* __restrict__ P2, const float* __restrict__ pb2,
           float* __restrict__ out) {
    extern __shared__ float sm[];
    int tid = threadIdx.x;

    // ---- stage weights into K-paired u64 layouts ----
    {
        u64* W1p = reinterpret_cast<u64*>(sm + OFF_W1);
        for (int idx = tid; idx < 8192; idx += THREADS) {
            int t = idx >> 7, j = idx & 127;
            W1p[idx] = pack2(W1[(2 * t) * 128 + j], W1[(2 * t + 1) * 128 + j]);
        }
        u64* W2p = reinterpret_cast<u64*>(sm + OFF_W2);
        for (int idx = tid; idx < 4096; idx += THREADS) {
            int t = idx >> 6, j = idx & 63;
            W2p[idx] = pack2(W2[(2 * t) * 64 + j], W2[(2 * t + 1) * 64 + j]);
        }
        u64* W3p = reinterpret_cast<u64*>(sm + OFF_W3);
        for (int idx = tid; idx < 2176; idx += THREADS) {
            int t = idx / 68, j = idx - t * 68;
            W3p[idx] = (j < 67)
                ? pack2(W3[(2 * t) * 67 + j], W3[(2 * t + 1) * 67 + j]) : 0ull;
        }
        u64* P1p = reinterpret_cast<u64*>(sm + OFF_P1);
        for (int idx = tid; idx < 1024; idx += THREADS) {
            int t = idx >> 5, j = idx & 31;
            P1p[idx] = pack2(P1[(2 * t) * 32 + j], P1[(2 * t + 1) * 32 + j]);
        }
    }
    for (int i = tid; i < 128; i += THREADS) sm[OFF_B1 + i] = b1[i];
    for (int i = tid; i < 64;  i += THREADS) sm[OFF_B2 + i] = b2[i];
    for (int i = tid; i < 67;  i += THREADS) sm[OFF_B3 + i] = b3[i];
    for (int i = tid; i < 32;  i += THREADS) sm[OFF_PB1 + i] = pb1[i];
    for (int i = tid; i < 32;  i += THREADS) sm[OFF_P2 + i] = P2[i];
    if (tid == 0) sm[OFF_PB2] = pb2[0];
    __syncthreads();

    int warpId = tid >> 5;
    int lane   = tid & 31;
    float* buf = sm + OFF_SCR + warpId * (NPW * 128);   // [NPW][128] ping-pong
    float4* buf4 = reinterpret_cast<float4*>(buf);
    ulonglong2* bufp = reinterpret_cast<ulonglong2*>(buf);  // [NPW][32] pairs

    const ulonglong2* sW1p2 = reinterpret_cast<const ulonglong2*>(sm + OFF_W1);
    const ulonglong2* sW2p2 = reinterpret_cast<const ulonglong2*>(sm + OFF_W2);
    const u64*        sW3p  = reinterpret_cast<const u64*>(sm + OFF_W3);
    const u64*        sP1p  = reinterpret_cast<const u64*>(sm + OFF_P1);
    const float4*     sb1_4 = reinterpret_cast<const float4*>(sm + OFF_B1);

    const int cnt = g_cnt;
    const int totalWarps = gridDim.x * WARPS;

    for (int g = blockIdx.x * WARPS + warpId; g * NPW < cnt; g += totalWarps) {
        int nn[NPW];
        bool valid[NPW];
        #pragma unroll
        for (int q = 0; q < NPW; q++) {
            int li = g * NPW + q;
            valid[q] = li < cnt;
            nn[q] = g_list[valid[q] ? li : g * NPW];
        }

        // ---- ctx = [feat | nmean] ----
        #pragma unroll
        for (int q = 0; q < NPW; q++) {
            int n = nn[q];
            float inv = 1.f / fmaxf(g_deg[n], 1.f);
            buf[q * 128 + lane]      = nf[(size_t)n * 64 + lane];
            buf[q * 128 + 32 + lane] = nf[(size_t)n * 64 + 32 + lane];
            buf[q * 128 + 64 + lane] = g_nsum[(size_t)n * 64 + lane] * inv;
            buf[q * 128 + 96 + lane] = g_nsum[(size_t)n * 64 + 32 + lane] * inv;
        }
        __syncwarp();

        // ---- layer 1: 128 -> 128 relu. lane owns outs 4*lane..+3.
        //      K-paired accs: out = psum(acc). ----
        u64 a0[NPW], a1[NPW], a2[NPW], a3[NPW];
        {
            float4 bb = sb1_4[lane];
            u64 i0 = pack2(bb.x, 0.f), i1 = pack2(bb.y, 0.f);
            u64 i2 = pack2(bb.z, 0.f), i3 = pack2(bb.w, 0.f);
            #pragma unroll
            for (int q = 0; q < NPW; q++) {
                a0[q] = i0; a1[q] = i1; a2[q] = i2; a3[q] = i3;
            }
        }
        #pragma unroll 2
        for (int i4 = 0; i4 < 32; i4++) {          // 4 k per iter = 2 t-pairs
            int t0 = 2 * i4, t1 = 2 * i4 + 1;
            ulonglong2 wA0 = sW1p2[t0 * 64 + 2 * lane];
            ulonglong2 wA1 = sW1p2[t0 * 64 + 2 * lane + 1];
            ulonglong2 wB0 = sW1p2[t1 * 64 + 2 * lane];
            ulonglong2 wB1 = sW1p2[t1 * 64 + 2 * lane + 1];
            #pragma unroll
            for (int q = 0; q < NPW; q++) {
                ulonglong2 cp = bufp[q * 32 + i4];
                ffma2(a0[q], wA0.x, cp.x); ffma2(a1[q], wA0.y, cp.x);
                ffma2(a2[q], wA1.x, cp.x); ffma2(a3[q], wA1.y, cp.x);
                ffma2(a0[q], wB0.x, cp.y); ffma2(a1[q], wB0.y, cp.y);
                ffma2(a2[q], wB1.x, cp.y); ffma2(a3[q], wB1.y, cp.y);
            }
        }
        __syncwarp();
        #pragma unroll
        for (int q = 0; q < NPW; q++) {
            buf4[q * 32 + lane] = make_float4(
                fmaxf(psum(a0[q]), 0.f), fmaxf(psum(a1[q]), 0.f),
                fmaxf(psum(a2[q]), 0.f), fmaxf(psum(a3[q]), 0.f));
        }
        __syncwarp();

        // ---- layer 2: 128 -> 64 relu. lane owns outs 2*lane..+1 ----
        u64 c0[NPW], c1[NPW];
        {
            u64 i0 = pack2(sm[OFF_B2 + 2 * lane], 0.f);
            u64 i1 = pack2(sm[OFF_B2 + 2 * lane + 1], 0.f);
            #pragma unroll
            for (int q = 0; q < NPW; q++) { c0[q] = i0; c1[q] = i1; }
        }
        #pragma unroll 2
        for (int i4 = 0; i4 < 32; i4++) {
            int t0 = 2 * i4, t1 = 2 * i4 + 1;
            ulonglong2 w0 = sW2p2[t0 * 32 + lane];
            ulonglong2 w1 = sW2p2[t1 * 32 + lane];
            #pragma unroll
            for (int q = 0; q < NPW; q++) {
                ulonglong2 cp = bufp[q * 32 + i4];
                ffma2(c0[q], w0.x, cp.x); ffma2(c1[q], w0.y, cp.x);
                ffma2(c0[q], w1.x, cp.y); ffma2(c1[q], w1.y, cp.y);
            }
        }
        __syncwarp();
        #pragma unroll
        for (int q = 0; q < NPW; q++) {
            reinterpret_cast<float2*>(buf)[q * 64 + lane] = make_float2(
                fmaxf(psum(c0[q]), 0.f), fmaxf(psum(c1[q]), 0.f));
        }
        __syncwarp();

        // ---- layer 3: 64 -> 67. lane owns outs lane, lane+32, lane+64(<3) ----
        u64 g0[NPW], g1[NPW], g2[NPW];
        {
            u64 i0 = pack2(sm[OFF_B3 + lane], 0.f);
            u64 i1 = pack2(sm[OFF_B3 + 32 + lane], 0.f);
            u64 i2 = (lane < 3) ? pack2(sm[OFF_B3 + 64 + lane], 0.f) : 0ull;
            #pragma unroll
            for (int q = 0; q < NPW; q++) { g0[q] = i0; g1[q] = i1; g2[q] = i2; }
        }
        #pragma unroll 2
        for (int i4 = 0; i4 < 16; i4++) {          // 64 k total
            int t0 = 2 * i4, t1 = 2 * i4 + 1;
            u64 wa0 = sW3p[t0 * 68 + lane];
            u64 wa1 = sW3p[t0 * 68 + 32 + lane];
            u64 wa2 = (lane < 3) ? sW3p[t0 * 68 + 64 + lane] : 0ull;
            u64 wb0 = sW3p[t1 * 68 + lane];
            u64 wb1 = sW3p[t1 * 68 + 32 + lane];
            u64 wb2 = (lane < 3) ? sW3p[t1 * 68 + 64 + lane] : 0ull;
            #pragma unroll
            for (int q = 0; q < NPW; q++) {
                ulonglong2 cp = bufp[q * 32 + i4];
                ffma2(g0[q], wa0, cp.x); ffma2(g1[q], wa1, cp.x);
                ffma2(g2[q], wa2, cp.x);
                ffma2(g0[q], wb0, cp.y); ffma2(g1[q], wb1, cp.y);
                ffma2(g2[q], wb2, cp.y);
            }
        }
        __syncwarp();

        // ---- write pos/feats to gmem; stash feats ALIGNED at buf[q*128+j] ----
        #pragma unroll
        for (int q = 0; q < NPW; q++) {
            float ga = psum(g0[q]), gb = psum(g1[q]), gc = psum(g2[q]);
            if (valid[q]) {
                float* o = out + (size_t)nn[q] * OUTW;
                o[lane]      = ga;
                o[32 + lane] = gb;
                if (lane < 3) o[64 + lane] = gc;
            }
            if (lane >= 3) buf[q * 128 + lane - 3] = ga;
            buf[q * 128 + lane + 29] = gb;
            if (lane < 3) buf[q * 128 + lane + 61] = gc;
        }
        __syncwarp();

        // ---- head: feats(64, aligned) -> 32 relu -> 1 sigmoid ----
        u64 p0[NPW];
        {
            u64 ii = pack2(sm[OFF_PB1 + lane], 0.f);
            #pragma unroll
            for (int q = 0; q < NPW; q++) p0[q] = ii;
        }
        #pragma unroll 2
        for (int i4 = 0; i4 < 16; i4++) {
            int t0 = 2 * i4, t1 = 2 * i4 + 1;
            u64 w0 = sP1p[t0 * 32 + lane];
            u64 w1 = sP1p[t1 * 32 + lane];
            #pragma unroll
            for (int q = 0; q < NPW; q++) {
                ulonglong2 cp = bufp[q * 32 + i4];
                ffma2(p0[q], w0, cp.x);
                ffma2(p0[q], w1, cp.y);
            }
        }
        float w2s = sm[OFF_P2 + lane];
        float pb2v = sm[OFF_PB2];
        #pragma unroll
        for (int q = 0; q < NPW; q++) {
            float v = fmaxf(psum(p0[q]), 0.f) * w2s;
            #pragma unroll
            for (int o = 16; o > 0; o >>= 1)
                v += __shfl_xor_sync(0xffffffffu, v, o);
            if (lane == 0 && valid[q])
                out[(size_t)nn[q] * OUTW + 67] =
                    1.f / (1.f + expf(-(v + pb2v)));
        }
        __syncwarp();
    }
}

// ---------------------------------------------------------------------------
extern "C" void kernel_launch(void* const* d_in, const int* in_sizes, int n_in,
                              void* d_out, int out_size) {
    const float* nf  = (const float*)d_in[0];
    const float* ops = (const float*)d_in[1];
    const int*   ei  = (const int*)d_in[2];
    const float* W1  = (const float*)d_in[3];
    const float* b1  = (const float*)d_in[4];
    const float* W2  = (const float*)d_in[5];
    const float* b2  = (const float*)d_in[6];
    const float* W3  = (const float*)d_in[7];
    const float* b3  = (const float*)d_in[8];
    const float* P1  = (const float*)d_in[9];
    const float* pb1 = (const float*)d_in[10];
    const float* P2  = (const float*)d_in[11];
    const float* pb2 = (const float*)d_in[12];
    float* out = (float*)d_out;

    int E = in_sizes[2] / 2;

    cudaMemsetAsync(d_out, 0, (size_t)out_size * sizeof(float));

    pmask_kernel<<<(N_NODES + 255) / 256, 256>>>(ops);

    int tthreads = 2 * E;
    edge_kernel<<<(tthreads + 255) / 256, 256>>>(ei, (const float4*)nf, E);

    compact_kernel<<<(N_NODES + 255) / 256, 256>>>();

    static_assert(SMEM_FLOATS * 4 <= 227 * 1024, "smem");
    cudaFuncSetAttribute(mlp_kernel,
                         cudaFuncAttributeMaxDynamicSharedMemorySize,
                         SMEM_FLOATS * 4);
    mlp_kernel<<<152, THREADS, SMEM_FLOATS * 4>>>(
        nf, W1, b1, W2, b2, W3, b3, P1, pb1, P2, pb2, out);
}

// round 9
// speedup vs baseline: 1.0865x; 1.0030x over previous
#include <cuda_runtime.h>
#include <cstdint>

#define N_NODES 100000
#define OUTW 68
typedef unsigned long long u64;

__device__ float g_nsum[(size_t)N_NODES * 64];
__device__ float g_deg[N_NODES];
__device__ unsigned g_pmaskbits[3136];
__device__ int g_list[N_NODES];
__device__ int g_cnt;

__device__ __forceinline__ u64 pack2(float a, float b) {
    u64 r; asm("mov.b64 %0, {%1, %2};" : "=l"(r) : "f"(a), "f"(b)); return r;
}
__device__ __forceinline__ void ffma2(u64& d, u64 a, u64 b) {
    asm("fma.rn.f32x2 %0, %1, %2, %3;" : "=l"(d) : "l"(a), "l"(b), "l"(d));
}
__device__ __forceinline__ float psum(u64 v) {
    float a, b;
    asm("mov.b64 {%0, %1}, %2;" : "=f"(a), "=f"(b) : "l"(v));
    return a + b;
}

// ---------------------------------------------------------------------------
// Kernel 1: softmax gate -> bit mask, zero deg, zero nsum rows of masked nodes
// ---------------------------------------------------------------------------
__global__ void pmask_kernel(const float* __restrict__ ops) {
    int n = blockIdx.x * blockDim.x + threadIdx.x;
    if (n == 0) g_cnt = 0;
    bool msk = false;
    if (n < N_NODES) {
        float o0 = ops[n * 4 + 0], o1 = ops[n * 4 + 1];
        float o2 = ops[n * 4 + 2], o3 = ops[n * 4 + 3];
        float mx = fmaxf(fmaxf(o0, o1), fmaxf(o2, o3));
        float e0 = expf(o0 - mx), e1 = expf(o1 - mx);
        float e2 = expf(o2 - mx), e3 = expf(o3 - mx);
        float p0 = e0 / (e0 + e1 + e2 + e3);
        msk = (p0 > 0.5f);
        g_deg[n] = 0.f;
    }
    unsigned bits = __ballot_sync(0xffffffffu, msk);
    if ((threadIdx.x & 31) == 0 && (n & ~31) < N_NODES)
        g_pmaskbits[n >> 5] = bits;
    if (msk) {
        float4 z = make_float4(0.f, 0.f, 0.f, 0.f);
        float4* row = reinterpret_cast<float4*>(g_nsum) + (size_t)n * 16;
        #pragma unroll
        for (int c = 0; c < 16; c++) row[c] = z;
    }
}

// ---------------------------------------------------------------------------
// Kernel 2: gated edge scatter, ballot redistribution 4 items/iter
// ---------------------------------------------------------------------------
__global__ void edge_kernel(const int* __restrict__ ei,
                            const float4* __restrict__ feat4,
                            int E) {
    int t = blockIdx.x * blockDim.x + threadIdx.x;
    int lane = threadIdx.x & 31;
    bool active = false;
    int tgt = 0, srcn = 0;
    if (t < 2 * E) {
        int e = t >> 1, dir = t & 1;
        int s = __ldg(&ei[e]);
        int d = __ldg(&ei[E + e]);
        tgt  = dir ? d : s;
        srcn = dir ? s : d;
        active = (g_pmaskbits[tgt >> 5] >> (tgt & 31)) & 1;
    }
    unsigned m = __ballot_sync(0xffffffffu, active);
    float4* nsum4 = reinterpret_cast<float4*>(g_nsum);
    int grp = lane >> 3;
    int c = lane & 7;
    while (m) {
        int b0 = -1, b1 = -1, b2 = -1, b3 = -1;
        b0 = __ffs(m) - 1; m &= m - 1;
        if (m) { b1 = __ffs(m) - 1; m &= m - 1; }
        if (m) { b2 = __ffs(m) - 1; m &= m - 1; }
        if (m) { b3 = __ffs(m) - 1; m &= m - 1; }
        int myb = (grp == 0) ? b0 : (grp == 1) ? b1 : (grp == 2) ? b2 : b3;
        int bb = (myb >= 0) ? myb : b0;
        int T = __shfl_sync(0xffffffffu, tgt,  bb);
        int S = __shfl_sync(0xffffffffu, srcn, bb);
        if (myb >= 0) {
            float4 v0 = __ldg(&feat4[(size_t)S * 16 + c]);
            float4 v1 = __ldg(&feat4[(size_t)S * 16 + c + 8]);
            asm volatile("red.global.add.v4.f32 [%0], {%1,%2,%3,%4};" ::
                         "l"(nsum4 + (size_t)T * 16 + c),
                         "f"(v0.x), "f"(v0.y), "f"(v0.z), "f"(v0.w) : "memory");
            asm volatile("red.global.add.v4.f32 [%0], {%1,%2,%3,%4};" ::
                         "l"(nsum4 + (size_t)T * 16 + c + 8),
                         "f"(v1.x), "f"(v1.y), "f"(v1.z), "f"(v1.w) : "memory");
            if (c == 0) atomicAdd(&g_deg[T], 1.f);
        }
    }
}

// ---------------------------------------------------------------------------
// Kernel 3: compact active nodes (warp-aggregated atomic)
// ---------------------------------------------------------------------------
__global__ void compact_kernel() {
    int n = blockIdx.x * blockDim.x + threadIdx.x;
    int lane = threadIdx.x & 31;
    bool act = false;
    if (n < N_NODES)
        act = ((g_pmaskbits[n >> 5] >> (n & 31)) & 1) && (g_deg[n] > 0.f);
    unsigned m = __ballot_sync(0xffffffffu, act);
    int base = 0;
    if (lane == 0 && m) base = atomicAdd(&g_cnt, __popc(m));
    base = __shfl_sync(0xffffffffu, base, 0);
    if (act) g_list[base + __popc(m & ((1u << lane) - 1))] = n;
}

// ---------------------------------------------------------------------------
// Kernel 4: MLP. K-paired FFMA2, NPW=4 (short per-group stream), 24 warps
// (6/SMSP hides LDS latency; 3648 warps >= ~3250 groups -> 1 group/warp).
// Weight staging: coalesced float4 row-pair loads packed in regs, STS.128.
// ---------------------------------------------------------------------------
#define WARPS 24
#define THREADS (WARPS * 32)
#define NPW 4

#define OFF_W1   0          // u64[64][128] = 16384 floats
#define OFF_W2   16384      // u64[64][64]  = 8192
#define OFF_W3   24576      // u64[32][68]  = 4352
#define OFF_P1   28928      // u64[32][32]  = 2048
#define OFF_B1   30976      // 128
#define OFF_B2   31104      // 64
#define OFF_B3   31168      // 68
#define OFF_PB1  31236      // 32
#define OFF_P2   31268      // 32
#define OFF_PB2  31300      // 1 (+3 pad)
#define OFF_SCR  31304      // per-warp: NPW*128 floats (2 KB)
#define SMEM_FLOATS (OFF_SCR + WARPS * NPW * 128)

__global__ void __launch_bounds__(THREADS, 1)
mlp_kernel(const float* __restrict__ nf,
           const float* __restrict__ W1, const float* __restrict__ b1,
           const float* __restrict__ W2, const float* __restrict__ b2,
           const float* __restrict__ W3, const float* __restrict__ b3,
           const float* __restrict__ P1, const float* __restrict__ pb1,
           const float* __restrict__ P2, const float* __restrict__ pb2,
           float* __restrict__ out) {
    extern __shared__ float sm[];
    int tid = threadIdx.x;

    // ---- coalesced K-paired staging ----
    {
        const float4* W1_4 = reinterpret_cast<const float4*>(W1);
        u64* W1p = reinterpret_cast<u64*>(sm + OFF_W1);
        for (int idx = tid; idx < 2048; idx += THREADS) {
            int t = idx >> 5, jv = idx & 31;
            float4 a = W1_4[(2 * t) * 32 + jv];
            float4 b = W1_4[(2 * t + 1) * 32 + jv];
            ulonglong2* dst = reinterpret_cast<ulonglong2*>(W1p + t * 128 + 4 * jv);
            dst[0] = make_ulonglong2(pack2(a.x, b.x), pack2(a.y, b.y));
            dst[1] = make_ulonglong2(pack2(a.z, b.z), pack2(a.w, b.w));
        }
        const float4* W2_4 = reinterpret_cast<const float4*>(W2);
        u64* W2p = reinterpret_cast<u64*>(sm + OFF_W2);
        for (int idx = tid; idx < 1024; idx += THREADS) {
            int t = idx >> 4, jv = idx & 15;
            float4 a = W2_4[(2 * t) * 16 + jv];
            float4 b = W2_4[(2 * t + 1) * 16 + jv];
            ulonglong2* dst = reinterpret_cast<ulonglong2*>(W2p + t * 64 + 4 * jv);
            dst[0] = make_ulonglong2(pack2(a.x, b.x), pack2(a.y, b.y));
            dst[1] = make_ulonglong2(pack2(a.z, b.z), pack2(a.w, b.w));
        }
        u64* W3p = reinterpret_cast<u64*>(sm + OFF_W3);
        for (int idx = tid; idx < 2176; idx += THREADS) {
            int t = idx / 68, j = idx - t * 68;
            W3p[idx] = (j < 67)
                ? pack2(W3[(2 * t) * 67 + j], W3[(2 * t + 1) * 67 + j]) : 0ull;
        }
        const float4* P1_4 = reinterpret_cast<const float4*>(P1);
        u64* P1p = reinterpret_cast<u64*>(sm + OFF_P1);
        for (int idx = tid; idx < 256; idx += THREADS) {
            int t = idx >> 3, jv = idx & 7;
            float4 a = P1_4[(2 * t) * 8 + jv];
            float4 b = P1_4[(2 * t + 1) * 8 + jv];
            ulonglong2* dst = reinterpret_cast<ulonglong2*>(P1p + t * 32 + 4 * jv);
            dst[0] = make_ulonglong2(pack2(a.x, b.x), pack2(a.y, b.y));
            dst[1] = make_ulonglong2(pack2(a.z, b.z), pack2(a.w, b.w));
        }
    }
    for (int i = tid; i < 128; i += THREADS) sm[OFF_B1 + i] = b1[i];
    for (int i = tid; i < 64;  i += THREADS) sm[OFF_B2 + i] = b2[i];
    for (int i = tid; i < 67;  i += THREADS) sm[OFF_B3 + i] = b3[i];
    for (int i = tid; i < 32;  i += THREADS) sm[OFF_PB1 + i] = pb1[i];
    for (int i = tid; i < 32;  i += THREADS) sm[OFF_P2 + i] = P2[i];
    if (tid == 0) sm[OFF_PB2] = pb2[0];
    __syncthreads();

    int warpId = tid >> 5;
    int lane   = tid & 31;
    float* buf = sm + OFF_SCR + warpId * (NPW * 128);
    float4* buf4 = reinterpret_cast<float4*>(buf);
    ulonglong2* bufp = reinterpret_cast<ulonglong2*>(buf);

    const ulonglong2* sW1p2 = reinterpret_cast<const ulonglong2*>(sm + OFF_W1);
    const ulonglong2* sW2p2 = reinterpret_cast<const ulonglong2*>(sm + OFF_W2);
    const u64*        sW3p  = reinterpret_cast<const u64*>(sm + OFF_W3);
    const u64*        sP1p  = reinterpret_cast<const u64*>(sm + OFF_P1);
    const float4*     sb1_4 = reinterpret_cast<const float4*>(sm + OFF_B1);

    const int cnt = g_cnt;
    const int totalWarps = gridDim.x * WARPS;

    for (int g = blockIdx.x * WARPS + warpId; g * NPW < cnt; g += totalWarps) {
        int nn[NPW];
        bool valid[NPW];
        #pragma unroll
        for (int q = 0; q < NPW; q++) {
            int li = g * NPW + q;
            valid[q] = li < cnt;
            nn[q] = g_list[valid[q] ? li : g * NPW];
        }

        // ---- ctx = [feat | nmean] ----
        #pragma unroll
        for (int q = 0; q < NPW; q++) {
            int n = nn[q];
            float inv = 1.f / fmaxf(g_deg[n], 1.f);
            buf[q * 128 + lane]      = nf[(size_t)n * 64 + lane];
            buf[q * 128 + 32 + lane] = nf[(size_t)n * 64 + 32 + lane];
            buf[q * 128 + 64 + lane] = g_nsum[(size_t)n * 64 + lane] * inv;
            buf[q * 128 + 96 + lane] = g_nsum[(size_t)n * 64 + 32 + lane] * inv;
        }
        __syncwarp();

        // ---- layer 1: 128 -> 128 relu. K-paired accs ----
        u64 a0[NPW], a1[NPW], a2[NPW], a3[NPW];
        {
            float4 bb = sb1_4[lane];
            u64 i0 = pack2(bb.x, 0.f), i1 = pack2(bb.y, 0.f);
            u64 i2 = pack2(bb.z, 0.f), i3 = pack2(bb.w, 0.f);
            #pragma unroll
            for (int q = 0; q < NPW; q++) {
                a0[q] = i0; a1[q] = i1; a2[q] = i2; a3[q] = i3;
            }
        }
        #pragma unroll 4
        for (int i4 = 0; i4 < 32; i4++) {
            int t0 = 2 * i4, t1 = 2 * i4 + 1;
            ulonglong2 wA0 = sW1p2[t0 * 64 + 2 * lane];
            ulonglong2 wA1 = sW1p2[t0 * 64 + 2 * lane + 1];
            ulonglong2 wB0 = sW1p2[t1 * 64 + 2 * lane];
            ulonglong2 wB1 = sW1p2[t1 * 64 + 2 * lane + 1];
            #pragma unroll
            for (int q = 0; q < NPW; q++) {
                ulonglong2 cp = bufp[q * 32 + i4];
                ffma2(a0[q], wA0.x, cp.x); ffma2(a1[q], wA0.y, cp.x);
                ffma2(a2[q], wA1.x, cp.x); ffma2(a3[q], wA1.y, cp.x);
                ffma2(a0[q], wB0.x, cp.y); ffma2(a1[q], wB0.y, cp.y);
                ffma2(a2[q], wB1.x, cp.y); ffma2(a3[q], wB1.y, cp.y);
            }
        }
        __syncwarp();
        #pragma unroll
        for (int q = 0; q < NPW; q++) {
            buf4[q * 32 + lane] = make_float4(
                fmaxf(psum(a0[q]), 0.f), fmaxf(psum(a1[q]), 0.f),
                fmaxf(psum(a2[q]), 0.f), fmaxf(psum(a3[q]), 0.f));
        }
        __syncwarp();

        // ---- layer 2: 128 -> 64 relu ----
        u64 c0[NPW], c1[NPW];
        {
            u64 i0 = pack2(sm[OFF_B2 + 2 * lane], 0.f);
            u64 i1 = pack2(sm[OFF_B2 + 2 * lane + 1], 0.f);
            #pragma unroll
            for (int q = 0; q < NPW; q++) { c0[q] = i0; c1[q] = i1; }
        }
        #pragma unroll 4
        for (int i4 = 0; i4 < 32; i4++) {
            int t0 = 2 * i4, t1 = 2 * i4 + 1;
            ulonglong2 w0 = sW2p2[t0 * 32 + lane];
            ulonglong2 w1 = sW2p2[t1 * 32 + lane];
            #pragma unroll
            for (int q = 0; q < NPW; q++) {
                ulonglong2 cp = bufp[q * 32 + i4];
                ffma2(c0[q], w0.x, cp.x); ffma2(c1[q], w0.y, cp.x);
                ffma2(c0[q], w1.x, cp.y); ffma2(c1[q], w1.y, cp.y);
            }
        }
        __syncwarp();
        #pragma unroll
        for (int q = 0; q < NPW; q++) {
            reinterpret_cast<float2*>(buf)[q * 64 + lane] = make_float2(
                fmaxf(psum(c0[q]), 0.f), fmaxf(psum(c1[q]), 0.f));
        }
        __syncwarp();

        // ---- layer 3: 64 -> 67 ----
        u64 g0[NPW], g1[NPW], g2[NPW];
        {
            u64 i0 = pack2(sm[OFF_B3 + lane], 0.f);
            u64 i1 = pack2(sm[OFF_B3 + 32 + lane], 0.f);
            u64 i2 = (lane < 3) ? pack2(sm[OFF_B3 + 64 + lane], 0.f) : 0ull;
            #pragma unroll
            for (int q = 0; q < NPW; q++) { g0[q] = i0; g1[q] = i1; g2[q] = i2; }
        }
        #pragma unroll 4
        for (int i4 = 0; i4 < 16; i4++) {
            int t0 = 2 * i4, t1 = 2 * i4 + 1;
            u64 wa0 = sW3p[t0 * 68 + lane];
            u64 wa1 = sW3p[t0 * 68 + 32 + lane];
            u64 wa2 = (lane < 3) ? sW3p[t0 * 68 + 64 + lane] : 0ull;
            u64 wb0 = sW3p[t1 * 68 + lane];
            u64 wb1 = sW3p[t1 * 68 + 32 + lane];
            u64 wb2 = (lane < 3) ? sW3p[t1 * 68 + 64 + lane] : 0ull;
            #pragma unroll
            for (int q = 0; q < NPW; q++) {
                ulonglong2 cp = bufp[q * 32 + i4];
                ffma2(g0[q], wa0, cp.x); ffma2(g1[q], wa1, cp.x);
                ffma2(g2[q], wa2, cp.x);
                ffma2(g0[q], wb0, cp.y); ffma2(g1[q], wb1, cp.y);
                ffma2(g2[q], wb2, cp.y);
            }
        }
        __syncwarp();

        #pragma unroll
        for (int q = 0; q < NPW; q++) {
            float ga = psum(g0[q]), gb = psum(g1[q]), gc = psum(g2[q]);
            if (valid[q]) {
                float* o = out + (size_t)nn[q] * OUTW;
                o[lane]      = ga;
                o[32 + lane] = gb;
                if (lane < 3) o[64 + lane] = gc;
            }
            if (lane >= 3) buf[q * 128 + lane - 3] = ga;
            buf[q * 128 + lane + 29] = gb;
            if (lane < 3) buf[q * 128 + lane + 61] = gc;
        }
        __syncwarp();

        // ---- head: feats(64, aligned) -> 32 relu -> 1 sigmoid ----
        u64 p0[NPW];
        {
            u64 ii = pack2(sm[OFF_PB1 + lane], 0.f);
            #pragma unroll
            for (int q = 0; q < NPW; q++) p0[q] = ii;
        }
        #pragma unroll 4
        for (int i4 = 0; i4 < 16; i4++) {
            int t0 = 2 * i4, t1 = 2 * i4 + 1;
            u64 w0 = sP1p[t0 * 32 + lane];
            u64 w1 = sP1p[t1 * 32 + lane];
            #pragma unroll
            for (int q = 0; q < NPW; q++) {
                ulonglong2 cp = bufp[q * 32 + i4];
                ffma2(p0[q], w0, cp.x);
                ffma2(p0[q], w1, cp.y);
            }
        }
        float w2s = sm[OFF_P2 + lane];
        float pb2v = sm[OFF_PB2];
        #pragma unroll
        for (int q = 0; q < NPW; q++) {
            float v = fmaxf(psum(p0[q]), 0.f) * w2s;
            #pragma unroll
            for (int o = 16; o > 0; o >>= 1)
                v += __shfl_xor_sync(0xffffffffu, v, o);
            if (lane == 0 && valid[q])
                out[(size_t)nn[q] * OUTW + 67] =
                    1.f / (1.f + expf(-(v + pb2v)));
        }
        __syncwarp();
    }
}

// ---------------------------------------------------------------------------
extern "C" void kernel_launch(void* const* d_in, const int* in_sizes, int n_in,
                              void* d_out, int out_size) {
    const float* nf  = (const float*)d_in[0];
    const float* ops = (const float*)d_in[1];
    const int*   ei  = (const int*)d_in[2];
    const float* W1  = (const float*)d_in[3];
    const float* b1  = (const float*)d_in[4];
    const float* W2  = (const float*)d_in[5];
    const float* b2  = (const float*)d_in[6];
    const float* W3  = (const float*)d_in[7];
    const float* b3  = (const float*)d_in[8];
    const float* P1  = (const float*)d_in[9];
    const float* pb1 = (const float*)d_in[10];
    const float* P2  = (const float*)d_in[11];
    const float* pb2 = (const float*)d_in[12];
    float* out = (float*)d_out;

    int E = in_sizes[2] / 2;

    cudaMemsetAsync(d_out, 0, (size_t)out_size * sizeof(float));

    pmask_kernel<<<(N_NODES + 255) / 256, 256>>>(ops);

    int tthreads = 2 * E;
    edge_kernel<<<(tthreads + 255) / 256, 256>>>(ei, (const float4*)nf, E);

    compact_kernel<<<(N_NODES + 255) / 256, 256>>>();

    static_assert(SMEM_FLOATS * 4 <= 227 * 1024, "smem");
    cudaFuncSetAttribute(mlp_kernel,
                         cudaFuncAttributeMaxDynamicSharedMemorySize,
                         SMEM_FLOATS * 4);
    mlp_kernel<<<152, THREADS, SMEM_FLOATS * 4>>>(
        nf, W1, b1, W2, b2, W3, b3, P1, pb1, P2, pb2, out);
}